// round 10
// baseline (speedup 1.0000x reference)
#include <cuda_runtime.h>

// Problem constants (fixed by the dataset)
#define NB   64          // batch
#define T1   4097        // maxT+1
#define MAXT 4096
#define HB   16          // hidden states
#define CL   32          // chunk length (steps per chunk)
#define BPB  16          // blocks per batch (consumer)
#define NMB  16          // block-level matrices per batch

// Dense gathered action logps, c-major: g_al[b][c][j], j = step-1 (j in [0,4095)).
// 4-step groups start at j % 4 == 0 -> 16B-aligned float4 loads.
__device__ float g_al[NB * HB * 4096];         // 16 MB
__device__ float g_mats[NB * NMB * HB * HB];   // 1 MB
__device__ float g_lam[NB * NMB * HB];
__device__ float g_partial[NB];
__device__ int   g_cnt[NB];     // zero-init; self-resetting each call
__device__ int   g_cnt2;        // zero-init; self-resetting each call

__device__ __forceinline__ float ldcg(const float* p) {
    float v; asm volatile("ld.global.cg.f32 %0,[%1];" : "=f"(v) : "l"(p)); return v;
}
__device__ __forceinline__ float4 ldcg4(const float* p) {
    float4 v;
    asm volatile("ld.global.cg.v4.f32 {%0,%1,%2,%3},[%4];"
                 : "=f"(v.x), "=f"(v.y), "=f"(v.z), "=f"(v.w) : "l"(p));
    return v;
}

// ===========================================================================
// Pass 1: scattered gather -> dense c-major g_al.
// Thread -> (b, c, 8-step octet). Reads 8 scattered alogp values (high MLP),
// writes 2 dense float4 (coalesced across threads: adjacent threads own
// adjacent octets of the same (b,c) row).
// ===========================================================================
__global__ __launch_bounds__(256) void hmm_gather(
    const float* __restrict__ alogp,
    const int* __restrict__ actions,
    const int* __restrict__ lengths)
{
    unsigned tid = blockIdx.x * 256u + threadIdx.x;  // 64*16*512 = 524288
    unsigned oct = tid & 511u;          // 512 octets of 8 steps
    unsigned c   = (tid >> 9) & 15u;
    unsigned b   = tid >> 13;
    unsigned len = (unsigned)__ldg(lengths + b);
    unsigned j0  = oct * 8u;

    float v[8];
#pragma unroll
    for (int u = 0; u < 8; ++u) {
        unsigned j = j0 + u;            // step i = j+1
        unsigned i = j + 1u;
        if (i < len && j < 4095u) {
            int a = __ldg(actions + (b << 12) + i);
            size_t src = ((size_t)(b * T1 + i) * 16 + c) * 18 + (unsigned)a;
            v[u] = __ldg(alogp + src);
        } else v[u] = 0.0f;
    }
    float4* dst = (float4*)(g_al + ((size_t)(b * 16 + c) << 12) + j0);
    dst[0] = make_float4(v[0], v[1], v[2], v[3]);
    dst[1] = make_float4(v[4], v[5], v[6], v[7]);
}

// ===========================================================================
// Pass 2: fused chunk + hierarchical fold + last-block tree combine.
// ===========================================================================

// Prefetch bank: 4 steps of (stop.xy, start) + one dense float4 of al.
struct PFB { float2 s[4]; float t[4]; float a[4]; };

__device__ __forceinline__ void load_group(
    int g0, int nact, unsigned idx16_0, const float* __restrict__ alrow,
    const float2* __restrict__ stop2, const float* __restrict__ startl,
    PFB& B)
{
    if (g0 < nact) {   // warp-uniform within half? g0 uniform; nact per-half: guard per half below
        float4 a4 = *(const float4*)(alrow + g0);   // aligned; may contain unused garbage past nact
        B.a[0] = a4.x; B.a[1] = a4.y; B.a[2] = a4.z; B.a[3] = a4.w;
    } else {
        B.a[0] = B.a[1] = B.a[2] = B.a[3] = 0.0f;
    }
#pragma unroll
    for (int u = 0; u < 4; ++u) {
        int t = g0 + u;
        if (t < nact) {
            unsigned idx = idx16_0 + (unsigned)t * 16u;
            B.s[u] = __ldg(stop2 + idx);     // (beta, omb)
            B.t[u] = __ldg(startl + idx);    // start
        } else {
            B.s[u] = make_float2(0.f, 0.f); B.t[u] = 0.f;
        }
    }
}

// Per step i (exact linear map):
//   s     = sum_j exp(beta_j) * p[j]
//   p[k] <- exp(al_k+start_k)*s + exp(al_k+omb_k)*p[k]
// Every 2 steps: p /= s, lam += log(s).
__device__ __forceinline__ void consume_group(
    int g0, int nsteps, int nact, int c, float* __restrict__ vb2,
    PFB& B, float (&p)[HB], float& lam)
{
#pragma unroll
    for (int u = 0; u < 4; ++u) {
        int t = g0 + u;
        if (t >= nsteps) return;   // nsteps is warp-uniform
        float eb   = __expf(B.s[u].x);
        float easv = __expf(B.a[u] + B.t[u]);
        float eaov = __expf(B.a[u] + B.s[u].y);
        float* vb = vb2 + (u & 1) * 48;
        vb[c]      = eb;
        vb[16 + c] = easv;
        vb[32 + c] = eaov;
        __syncwarp();
        const float4* EB = (const float4*)vb;
        float4 e0 = EB[0], e1 = EB[1], e2 = EB[2], e3 = EB[3];
        float t0 = fmaf(e0.x, p[0],  e0.y * p[1])  + fmaf(e0.z, p[2],  e0.w * p[3]);
        float t1 = fmaf(e1.x, p[4],  e1.y * p[5])  + fmaf(e1.z, p[6],  e1.w * p[7]);
        float t2 = fmaf(e2.x, p[8],  e2.y * p[9])  + fmaf(e2.z, p[10], e2.w * p[11]);
        float t3 = fmaf(e3.x, p[12], e3.y * p[13]) + fmaf(e3.z, p[14], e3.w * p[15]);
        float s = (t0 + t1) + (t2 + t3);
        if (t < nact) {            // uniform within each half-warp
            const float4* EA = (const float4*)(vb + 16);
            const float4* EO = (const float4*)(vb + 32);
            float4 a0 = EA[0], a1 = EA[1], a2 = EA[2], a3 = EA[3];
            float4 o0 = EO[0], o1 = EO[1], o2 = EO[2], o3 = EO[3];
            p[0]  = fmaf(o0.x, p[0],  a0.x * s);
            p[1]  = fmaf(o0.y, p[1],  a0.y * s);
            p[2]  = fmaf(o0.z, p[2],  a0.z * s);
            p[3]  = fmaf(o0.w, p[3],  a0.w * s);
            p[4]  = fmaf(o1.x, p[4],  a1.x * s);
            p[5]  = fmaf(o1.y, p[5],  a1.y * s);
            p[6]  = fmaf(o1.z, p[6],  a1.z * s);
            p[7]  = fmaf(o1.w, p[7],  a1.w * s);
            p[8]  = fmaf(o2.x, p[8],  a2.x * s);
            p[9]  = fmaf(o2.y, p[9],  a2.y * s);
            p[10] = fmaf(o2.z, p[10], a2.z * s);
            p[11] = fmaf(o2.w, p[11], a2.w * s);
            p[12] = fmaf(o3.x, p[12], a3.x * s);
            p[13] = fmaf(o3.y, p[13], a3.y * s);
            p[14] = fmaf(o3.z, p[14], a3.z * s);
            p[15] = fmaf(o3.w, p[15], a3.w * s);
            if (t & 1) {
                float r = __fdividef(1.0f, s);
                lam += __logf(s);
#pragma unroll
                for (int k = 0; k < HB; ++k) p[k] *= r;
            }
        }
    }
}

// Tree product: C_true = A_true * P_true (A later, P earlier).
__device__ __forceinline__ void mat_product2(
    const float* __restrict__ srcM, const float* __restrict__ srcLam,
    float* __restrict__ dstM, float* __restrict__ dstLam,
    int pidx, int lane, float* __restrict__ sw, bool from_gmem)
{
    const int c = lane & 15;
    const int h = lane >> 4;                    // rows [8h, 8h+8)
    const float* Pm = srcM + (size_t)(2 * pidx) * 256;
    const float* Am = srcM + (size_t)(2 * pidx + 1) * 256;
    float lamP, lamA;
    if (from_gmem) {
        lamP = ldcg(srcLam + (2 * pidx) * 16 + c);
        lamA = ldcg(srcLam + (2 * pidx + 1) * 16 + c);
    } else {
        lamP = srcLam[(2 * pidx) * 16 + c];
        lamA = srcLam[(2 * pidx + 1) * 16 + c];
    }
    float mA = lamA;
    mA = fmaxf(mA, __shfl_xor_sync(0xffffffffu, mA, 1));
    mA = fmaxf(mA, __shfl_xor_sync(0xffffffffu, mA, 2));
    mA = fmaxf(mA, __shfl_xor_sync(0xffffffffu, mA, 4));
    mA = fmaxf(mA, __shfl_xor_sync(0xffffffffu, mA, 8));
    if (lane < 16) sw[c] = __expf(lamA - mA);
    __syncwarp();
    float w[16];
#pragma unroll
    for (int j = 0; j < 16; ++j)
        w[j] = sw[j] * (from_gmem ? ldcg(Pm + j * 16 + c) : Pm[j * 16 + c]);
    __syncwarp();
    float Cv[8];
#pragma unroll
    for (int k8 = 0; k8 < 8; ++k8) {
        float4 a0, a1, a2, a3;
        const float* Ar = Am + (h * 8 + k8) * 16;
        if (from_gmem) { a0 = ldcg4(Ar); a1 = ldcg4(Ar + 4); a2 = ldcg4(Ar + 8); a3 = ldcg4(Ar + 12); }
        else { const float4* A4 = (const float4*)Ar; a0 = A4[0]; a1 = A4[1]; a2 = A4[2]; a3 = A4[3]; }
        float d0 = fmaf(a0.x, w[0],  a0.y * w[1])  + fmaf(a0.z, w[2],  a0.w * w[3]);
        float d1 = fmaf(a1.x, w[4],  a1.y * w[5])  + fmaf(a1.z, w[6],  a1.w * w[7]);
        float d2 = fmaf(a2.x, w[8],  a2.y * w[9])  + fmaf(a2.z, w[10], a2.w * w[11]);
        float d3 = fmaf(a3.x, w[12], a3.y * w[13]) + fmaf(a3.z, w[14], a3.w * w[15]);
        Cv[k8] = (d0 + d1) + (d2 + d3);
    }
    float s = Cv[0];
#pragma unroll
    for (int k8 = 1; k8 < 8; ++k8) s = fmaxf(s, Cv[k8]);
    s = fmaxf(s, __shfl_xor_sync(0xffffffffu, s, 16));   // combine halves
    float r = __fdividef(1.0f, s);
#pragma unroll
    for (int k8 = 0; k8 < 8; ++k8)
        dstM[pidx * 256 + (h * 8 + k8) * 16 + c] = Cv[k8] * r;
    if (lane < 16) dstLam[pidx * 16 + c] = lamP + mA + __logf(s);
}

// Smem union: chunk-phase scratch vs combine X buffer (never simultaneous).
union __align__(16) SmemU {
    struct {
        float vec[4][2][2][3 * HB];
        float m1[4][HB][HB + 1];
        float lam1[4][HB];
    } ck;
    struct {
        float X[8 * 256];
        float lamX[8 * 16];
    } cb;
};

__global__ __launch_bounds__(128, 6) void hmm_fused(
    const float* __restrict__ alogp,
    const float* __restrict__ stopl,
    const float* __restrict__ startl,
    const int* __restrict__ actions,
    const int* __restrict__ lengths,
    float* __restrict__ out)
{
    const int wib  = threadIdx.x >> 5;
    const int lane = threadIdx.x & 31;
    const int b    = blockIdx.x >> 4;             // 64 batches
    const int blk  = blockIdx.x & 15;             // 16 blocks per batch
    const int pr   = blk * 4 + wib;               // 64 chunk-pairs per batch
    const int sub  = lane >> 4;
    const int c    = lane & 15;
    const int ch   = pr * 2 + sub;                // 128 chunks per batch
    const int i0   = 1 + ch * CL;

    __shared__ SmemU U;
    __shared__ __align__(16) float bm[6 * 256];
    __shared__ float lamB[6 * 16];
    __shared__ __align__(16) float sw[4][16];
    __shared__ int s_last, s_last2;

    const int len = lengths[b];

    // ---- chunk phase (one chunk per half-warp) ----
    int cnt  = min(CL, MAXT - i0);
    int nact = max(0, min(len - i0, cnt));
    const int i0p  = 1 + pr * 2 * CL;
    int n0 = max(0, min(len - i0p, min(CL, MAXT - i0p)));
    int n1 = max(0, min(len - (i0p + CL), min(CL, MAXT - (i0p + CL))));
    int nsteps = max(n0, n1);

    float p[HB];
#pragma unroll
    for (int k = 0; k < HB; ++k) p[k] = (k == c) ? 1.0f : 0.0f;
    float lam = 0.0f;

    if (nsteps > 0) {
        const unsigned idx16_0 = ((unsigned)b * T1 + (unsigned)i0) * 16u + (unsigned)c;
        const float2* stop2 = (const float2*)stopl;
        // dense al row for this chunk: slot j = i-1 = ch*CL + t
        const float* alrow = g_al + ((size_t)(b * 16 + c) << 12) + (unsigned)(ch * CL);
        float* vb2 = &U.ck.vec[wib][sub][0][0];

        PFB B0, B1;
        load_group(0, nact, idx16_0, alrow, stop2, startl, B0);
        for (int g0 = 0; g0 < nsteps; g0 += 8) {
            load_group(g0 + 4, nact, idx16_0, alrow, stop2, startl, B1);
            consume_group(g0, nsteps, nact, c, vb2, B0, p, lam);
            load_group(g0 + 8, nact, idx16_0, alrow, stop2, startl, B0);
            consume_group(g0 + 4, nsteps, nact, c, vb2, B1, p, lam);
        }
    }

    // ---- warp fold: R_true = M1_true * M0_true -> smem bm[wib] ----
    __syncwarp();
    if (sub == 1) {
#pragma unroll
        for (int k = 0; k < HB; ++k) U.ck.m1[wib][c][k] = p[k];
        U.ck.lam1[wib][c] = lam;
    }
    __syncwarp();
    if (sub == 0) {
        float m1 = U.ck.lam1[wib][0];
#pragma unroll
        for (int j = 1; j < HB; ++j) m1 = fmaxf(m1, U.ck.lam1[wib][j]);
        float R[HB];
#pragma unroll
        for (int k = 0; k < HB; ++k) R[k] = 0.0f;
#pragma unroll
        for (int j = 0; j < HB; ++j) {
            float wj = p[j] * __expf(U.ck.lam1[wib][j] - m1);
            const float* Aj = &U.ck.m1[wib][j][0];
#pragma unroll
            for (int k = 0; k < HB; ++k) R[k] = fmaf(wj, Aj[k], R[k]);
        }
        float s = R[0];
#pragma unroll
        for (int k = 1; k < HB; ++k) s = fmaxf(s, R[k]);
        float r = __fdividef(1.0f, s);
#pragma unroll
        for (int k = 0; k < HB; ++k)
            bm[wib * 256 + k * 16 + c] = R[k] * r;
        lamB[wib * 16 + c] = lam + m1 + __logf(s);
    }
    __syncthreads();

    // ---- block fold: 4 warp-mats -> 1 block-mat -> gmem ----
    if (wib < 2)
        mat_product2(bm, lamB, bm + 4 * 256, lamB + 4 * 16, wib, lane, sw[wib], false);
    __syncthreads();
    if (wib == 0)
        mat_product2(bm + 4 * 256, lamB + 4 * 16,
                     g_mats + (size_t)(b * NMB + blk) * 256,
                     g_lam  + (size_t)(b * NMB + blk) * 16,
                     0, lane, sw[0], false);

    // ---- last-block election ----
    __threadfence();
    __syncthreads();
    if (threadIdx.x == 0) {
        int old = atomicAdd(&g_cnt[b], 1);
        s_last = (old == BPB - 1);
        if (old == BPB - 1) g_cnt[b] = 0;
    }
    __syncthreads();
    if (!s_last) return;

    // ---- tree combine over 16 block-mats ----
    float* X = U.cb.X; float* lamX = U.cb.lamX;
    float* Y = bm;     float* lamY = lamB;
    const float* gM = g_mats + (size_t)b * NMB * 256;
    const float* gL = g_lam  + (size_t)b * NMB * 16;

    mat_product2(gM, gL, X, lamX, wib,     lane, sw[wib], true);
    mat_product2(gM, gL, X, lamX, wib + 4, lane, sw[wib], true);
    __syncthreads();
    mat_product2(X, lamX, Y, lamY, wib, lane, sw[wib], false);
    __syncthreads();
    if (wib < 2) mat_product2(Y, lamY, X, lamX, wib, lane, sw[wib], false);
    __syncthreads();
    if (wib == 0) mat_product2(X, lamX, Y, lamY, 0, lane, sw[0], false);
    __syncthreads();

    if (wib == 0) {
        const size_t rb = (size_t)b * T1;
        const int a0i = actions[(size_t)b * MAXT];

        float f0 = startl[rb * 16 + c] + alogp[(rb * 16 + (size_t)c) * 18 + a0i];
        float t = lamY[c] + f0;
        float F0 = t;
        F0 = fmaxf(F0, __shfl_xor_sync(0xffffffffu, F0, 1));
        F0 = fmaxf(F0, __shfl_xor_sync(0xffffffffu, F0, 2));
        F0 = fmaxf(F0, __shfl_xor_sync(0xffffffffu, F0, 4));
        F0 = fmaxf(F0, __shfl_xor_sync(0xffffffffu, F0, 8));
        if (lane < 16) sw[0][c] = __expf(t - F0);
        __syncwarp();
        const float4* M4 = (const float4*)Y;
        const float4* W4 = (const float4*)sw[0];
        float4 m0 = M4[c * 4 + 0], m1 = M4[c * 4 + 1];
        float4 m2 = M4[c * 4 + 2], m3 = M4[c * 4 + 3];
        float4 w0 = W4[0], w1 = W4[1], w2 = W4[2], w3 = W4[3];
        float d0 = fmaf(m0.x, w0.x, m0.y * w0.y) + fmaf(m0.z, w0.z, m0.w * w0.w);
        float d1 = fmaf(m1.x, w1.x, m1.y * w1.y) + fmaf(m1.z, w1.z, m1.w * w1.w);
        float d2 = fmaf(m2.x, w2.x, m2.y * w2.y) + fmaf(m2.z, w2.z, m2.w * w2.w);
        float d3 = fmaf(m3.x, w3.x, m3.y * w3.y) + fmaf(m3.z, w3.z, m3.w * w3.w);
        float v = (d0 + d1) + (d2 + d3);

        float u = stopl[((rb + (size_t)len) * 16 + (size_t)c) * 2];
        float mS = u;
        mS = fmaxf(mS, __shfl_xor_sync(0xffffffffu, mS, 1));
        mS = fmaxf(mS, __shfl_xor_sync(0xffffffffu, mS, 2));
        mS = fmaxf(mS, __shfl_xor_sync(0xffffffffu, mS, 4));
        mS = fmaxf(mS, __shfl_xor_sync(0xffffffffu, mS, 8));
        float term = __expf(u - mS) * v;
        term += __shfl_xor_sync(0xffffffffu, term, 1);
        term += __shfl_xor_sync(0xffffffffu, term, 2);
        term += __shfl_xor_sync(0xffffffffu, term, 4);
        term += __shfl_xor_sync(0xffffffffu, term, 8);

        if (lane == 0) {
            g_partial[b] = -(F0 + mS + __logf(term));
            __threadfence();
            int old2 = atomicAdd(&g_cnt2, 1);
            s_last2 = (old2 == NB - 1);
            if (old2 == NB - 1) g_cnt2 = 0;
        }
    }
    __syncthreads();

    if (s_last2 && wib == 0) {
        float v = ldcg(&g_partial[lane]) + ldcg(&g_partial[lane + 32]);
        v += __shfl_xor_sync(0xffffffffu, v, 1);
        v += __shfl_xor_sync(0xffffffffu, v, 2);
        v += __shfl_xor_sync(0xffffffffu, v, 4);
        v += __shfl_xor_sync(0xffffffffu, v, 8);
        v += __shfl_xor_sync(0xffffffffu, v, 16);
        if (lane == 0) *out = v;
    }
}

extern "C" void kernel_launch(void* const* d_in, const int* in_sizes, int n_in,
                              void* d_out, int out_size)
{
    const float* alogp   = (const float*)d_in[0];
    const float* stopl   = (const float*)d_in[1];
    const float* startl  = (const float*)d_in[2];
    const int*   actions = (const int*)d_in[3];
    const int*   lengths = (const int*)d_in[4];
    float* out = (float*)d_out;

    hmm_gather<<<(NB * HB * 512) / 256, 256>>>(alogp, actions, lengths);
    hmm_fused<<<NB * BPB, 128>>>(alogp, stopl, startl, actions, lengths, out);
}

// round 11
// speedup vs baseline: 1.2185x; 1.2185x over previous
#include <cuda_runtime.h>

// Problem constants (fixed by the dataset)
#define NB   64          // batch
#define T1   4097        // maxT+1
#define MAXT 4096
#define HB   16          // hidden states
#define CL   32          // chunk length (steps per chunk)
#define BPB  16          // blocks per batch
#define NMB  16          // block-level matrices per batch

// Scratch: per (batch, block) folded transfer matrix (256 steps each).
__device__ float g_mats[NB * NMB * HB * HB];   // 1 MB
__device__ float g_lam[NB * NMB * HB];
__device__ float g_partial[NB];
__device__ int   g_cnt[NB];     // zero-init; self-resetting each call
__device__ int   g_cnt2;        // zero-init; self-resetting each call

__device__ __forceinline__ float ldcg(const float* p) {
    float v; asm volatile("ld.global.cg.f32 %0,[%1];" : "=f"(v) : "l"(p)); return v;
}
__device__ __forceinline__ float4 ldcg4(const float* p) {
    float4 v;
    asm volatile("ld.global.cg.v4.f32 {%0,%1,%2,%3},[%4];"
                 : "=f"(v.x), "=f"(v.y), "=f"(v.z), "=f"(v.w) : "l"(p));
    return v;
}

// Prefetch bank: 4 steps of (stop.xy, start, action_logp) per lane.
struct PFB { float2 s[4]; float t[4]; float a[4]; };

__device__ __forceinline__ void load_group(
    int g0, int nact, unsigned idx16_0,
    const float2* __restrict__ stop2, const float* __restrict__ startl,
    const float* __restrict__ alogp, const int* __restrict__ sa,
    PFB& B)
{
#pragma unroll
    for (int u = 0; u < 4; ++u) {
        int t = g0 + u;
        if (t < nact) {
            unsigned idx = idx16_0 + (unsigned)t * 16u;
            B.s[u] = __ldg(stop2 + idx);                         // (beta, omb)
            B.t[u] = __ldg(startl + idx);                        // start
            B.a[u] = __ldg(alogp + idx * 18u + (unsigned)sa[t]); // action logp
        } else {
            B.s[u] = make_float2(0.f, 0.f); B.t[u] = 0.f; B.a[u] = 0.f;
        }
    }
}

// Per step i (exact linear map):
//   s     = sum_j exp(beta_j) * p[j]
//   p[k] <- exp(al_k+start_k)*s + exp(al_k+omb_k)*p[k]
// Every 4 steps: p /= s, lam += log(s)  (conditioning; p*e^lam invariant;
// between renorms p stays within [~e^-120*max, ~1e5] -> fp32-safe; entries
// that flush are >=87 nats below the column max, i.e. logsumexp-negligible).
__device__ __forceinline__ void consume_group(
    int g0, int nsteps, int nact, int c, float* __restrict__ vb2,
    PFB& B, float (&p)[HB], float& lam)
{
#pragma unroll
    for (int u = 0; u < 4; ++u) {
        int t = g0 + u;
        if (t >= nsteps) return;   // nsteps is warp-uniform
        float eb   = __expf(B.s[u].x);
        float easv = __expf(B.a[u] + B.t[u]);
        float eaov = __expf(B.a[u] + B.s[u].y);
        float* vb = vb2 + (u & 1) * 48;
        vb[c]      = eb;
        vb[16 + c] = easv;
        vb[32 + c] = eaov;
        __syncwarp();
        const float4* EB = (const float4*)vb;
        float4 e0 = EB[0], e1 = EB[1], e2 = EB[2], e3 = EB[3];
        float t0 = fmaf(e0.x, p[0],  e0.y * p[1])  + fmaf(e0.z, p[2],  e0.w * p[3]);
        float t1 = fmaf(e1.x, p[4],  e1.y * p[5])  + fmaf(e1.z, p[6],  e1.w * p[7]);
        float t2 = fmaf(e2.x, p[8],  e2.y * p[9])  + fmaf(e2.z, p[10], e2.w * p[11]);
        float t3 = fmaf(e3.x, p[12], e3.y * p[13]) + fmaf(e3.z, p[14], e3.w * p[15]);
        float s = (t0 + t1) + (t2 + t3);
        if (t < nact) {            // uniform within each half-warp
            const float4* EA = (const float4*)(vb + 16);
            const float4* EO = (const float4*)(vb + 32);
            float4 a0 = EA[0], a1 = EA[1], a2 = EA[2], a3 = EA[3];
            float4 o0 = EO[0], o1 = EO[1], o2 = EO[2], o3 = EO[3];
            p[0]  = fmaf(o0.x, p[0],  a0.x * s);
            p[1]  = fmaf(o0.y, p[1],  a0.y * s);
            p[2]  = fmaf(o0.z, p[2],  a0.z * s);
            p[3]  = fmaf(o0.w, p[3],  a0.w * s);
            p[4]  = fmaf(o1.x, p[4],  a1.x * s);
            p[5]  = fmaf(o1.y, p[5],  a1.y * s);
            p[6]  = fmaf(o1.z, p[6],  a1.z * s);
            p[7]  = fmaf(o1.w, p[7],  a1.w * s);
            p[8]  = fmaf(o2.x, p[8],  a2.x * s);
            p[9]  = fmaf(o2.y, p[9],  a2.y * s);
            p[10] = fmaf(o2.z, p[10], a2.z * s);
            p[11] = fmaf(o2.w, p[11], a2.w * s);
            p[12] = fmaf(o3.x, p[12], a3.x * s);
            p[13] = fmaf(o3.y, p[13], a3.y * s);
            p[14] = fmaf(o3.z, p[14], a3.z * s);
            p[15] = fmaf(o3.w, p[15], a3.w * s);
            if ((t & 3) == 3) {
                float r = __fdividef(1.0f, s);
                lam += __logf(s);
#pragma unroll
                for (int k = 0; k < HB; ++k) p[k] *= r;
            }
        }
    }
}

// Tree product: C_true = A_true * P_true (A later, P earlier).
__device__ __forceinline__ void mat_product2(
    const float* __restrict__ srcM, const float* __restrict__ srcLam,
    float* __restrict__ dstM, float* __restrict__ dstLam,
    int pidx, int lane, float* __restrict__ sw, bool from_gmem)
{
    const int c = lane & 15;
    const int h = lane >> 4;                    // rows [8h, 8h+8)
    const float* Pm = srcM + (size_t)(2 * pidx) * 256;
    const float* Am = srcM + (size_t)(2 * pidx + 1) * 256;
    float lamP, lamA;
    if (from_gmem) {
        lamP = ldcg(srcLam + (2 * pidx) * 16 + c);
        lamA = ldcg(srcLam + (2 * pidx + 1) * 16 + c);
    } else {
        lamP = srcLam[(2 * pidx) * 16 + c];
        lamA = srcLam[(2 * pidx + 1) * 16 + c];
    }
    float mA = lamA;
    mA = fmaxf(mA, __shfl_xor_sync(0xffffffffu, mA, 1));
    mA = fmaxf(mA, __shfl_xor_sync(0xffffffffu, mA, 2));
    mA = fmaxf(mA, __shfl_xor_sync(0xffffffffu, mA, 4));
    mA = fmaxf(mA, __shfl_xor_sync(0xffffffffu, mA, 8));
    if (lane < 16) sw[c] = __expf(lamA - mA);
    __syncwarp();
    float w[16];
#pragma unroll
    for (int j = 0; j < 16; ++j)
        w[j] = sw[j] * (from_gmem ? ldcg(Pm + j * 16 + c) : Pm[j * 16 + c]);
    __syncwarp();
    float Cv[8];
#pragma unroll
    for (int k8 = 0; k8 < 8; ++k8) {
        float4 a0, a1, a2, a3;
        const float* Ar = Am + (h * 8 + k8) * 16;
        if (from_gmem) { a0 = ldcg4(Ar); a1 = ldcg4(Ar + 4); a2 = ldcg4(Ar + 8); a3 = ldcg4(Ar + 12); }
        else { const float4* A4 = (const float4*)Ar; a0 = A4[0]; a1 = A4[1]; a2 = A4[2]; a3 = A4[3]; }
        float d0 = fmaf(a0.x, w[0],  a0.y * w[1])  + fmaf(a0.z, w[2],  a0.w * w[3]);
        float d1 = fmaf(a1.x, w[4],  a1.y * w[5])  + fmaf(a1.z, w[6],  a1.w * w[7]);
        float d2 = fmaf(a2.x, w[8],  a2.y * w[9])  + fmaf(a2.z, w[10], a2.w * w[11]);
        float d3 = fmaf(a3.x, w[12], a3.y * w[13]) + fmaf(a3.z, w[14], a3.w * w[15]);
        Cv[k8] = (d0 + d1) + (d2 + d3);
    }
    float s = Cv[0];
#pragma unroll
    for (int k8 = 1; k8 < 8; ++k8) s = fmaxf(s, Cv[k8]);
    s = fmaxf(s, __shfl_xor_sync(0xffffffffu, s, 16));   // combine halves
    float r = __fdividef(1.0f, s);
#pragma unroll
    for (int k8 = 0; k8 < 8; ++k8)
        dstM[pidx * 256 + (h * 8 + k8) * 16 + c] = Cv[k8] * r;
    if (lane < 16) dstLam[pidx * 16 + c] = lamP + mA + __logf(s);
}

// Smem union: chunk-phase scratch vs combine X buffer (never simultaneous).
union __align__(16) SmemU {
    struct {
        float vec[4][2][2][3 * HB];
        float m1[4][HB][HB + 1];
        float lam1[4][HB];
    } ck;
    struct {
        float X[8 * 256];
        float lamX[8 * 16];
    } cb;
};

__global__ __launch_bounds__(128, 6) void hmm_fused(
    const float* __restrict__ alogp,
    const float* __restrict__ stopl,
    const float* __restrict__ startl,
    const int* __restrict__ actions,
    const int* __restrict__ lengths,
    float* __restrict__ out)
{
    const int wib  = threadIdx.x >> 5;
    const int lane = threadIdx.x & 31;
    const int b    = blockIdx.x >> 4;             // 64 batches
    const int blk  = blockIdx.x & 15;             // 16 blocks per batch
    const int pr   = blk * 4 + wib;               // 64 chunk-pairs per batch
    const int sub  = lane >> 4;
    const int c    = lane & 15;
    const int ch   = pr * 2 + sub;                // 128 chunks per batch
    const int i0   = 1 + ch * CL;

    __shared__ int s_act[4][2 * CL];
    __shared__ SmemU U;
    __shared__ __align__(16) float bm[6 * 256];
    __shared__ float lamB[6 * 16];
    __shared__ __align__(16) float sw[4][16];
    __shared__ int s_last, s_last2;

    const int len = lengths[b];

    // ---- chunk phase (one chunk per half-warp) ----
    int cnt  = min(CL, MAXT - i0);
    int nact = max(0, min(len - i0, cnt));
    const int i0p  = 1 + pr * 2 * CL;
    int n0 = max(0, min(len - i0p, min(CL, MAXT - i0p)));
    int n1 = max(0, min(len - (i0p + CL), min(CL, MAXT - (i0p + CL))));
    int nsteps = max(n0, n1);

    int totA = min(2 * CL, MAXT - i0p);
    for (int idx = lane; idx < totA; idx += 32)
        s_act[wib][idx] = actions[(size_t)b * MAXT + i0p + idx];
    __syncwarp();

    float p[HB];
#pragma unroll
    for (int k = 0; k < HB; ++k) p[k] = (k == c) ? 1.0f : 0.0f;
    float lam = 0.0f;

    if (nsteps > 0) {
        const unsigned idx16_0 = ((unsigned)b * T1 + (unsigned)i0) * 16u + (unsigned)c;
        const float2* stop2 = (const float2*)stopl;
        const int* sa = &s_act[wib][sub * CL];
        float* vb2 = &U.ck.vec[wib][sub][0][0];

        // 3-deep prefetch: 12 steps of lookahead (36 outstanding LDGs/warp)
        PFB B0, B1, B2;
        load_group(0, nact, idx16_0, stop2, startl, alogp, sa, B0);
        load_group(4, nact, idx16_0, stop2, startl, alogp, sa, B1);
        load_group(8, nact, idx16_0, stop2, startl, alogp, sa, B2);
        for (int g0 = 0; g0 < nsteps; g0 += 12) {
            consume_group(g0, nsteps, nact, c, vb2, B0, p, lam);
            load_group(g0 + 12, nact, idx16_0, stop2, startl, alogp, sa, B0);
            consume_group(g0 + 4, nsteps, nact, c, vb2, B1, p, lam);
            load_group(g0 + 16, nact, idx16_0, stop2, startl, alogp, sa, B1);
            consume_group(g0 + 8, nsteps, nact, c, vb2, B2, p, lam);
            load_group(g0 + 20, nact, idx16_0, stop2, startl, alogp, sa, B2);
        }
    }

    // ---- warp fold: R_true = M1_true * M0_true -> smem bm[wib] ----
    __syncwarp();
    if (sub == 1) {
#pragma unroll
        for (int k = 0; k < HB; ++k) U.ck.m1[wib][c][k] = p[k];
        U.ck.lam1[wib][c] = lam;
    }
    __syncwarp();
    if (sub == 0) {
        float m1 = U.ck.lam1[wib][0];
#pragma unroll
        for (int j = 1; j < HB; ++j) m1 = fmaxf(m1, U.ck.lam1[wib][j]);
        float R[HB];
#pragma unroll
        for (int k = 0; k < HB; ++k) R[k] = 0.0f;
#pragma unroll
        for (int j = 0; j < HB; ++j) {
            float wj = p[j] * __expf(U.ck.lam1[wib][j] - m1);
            const float* Aj = &U.ck.m1[wib][j][0];
#pragma unroll
            for (int k = 0; k < HB; ++k) R[k] = fmaf(wj, Aj[k], R[k]);
        }
        float s = R[0];
#pragma unroll
        for (int k = 1; k < HB; ++k) s = fmaxf(s, R[k]);
        float r = __fdividef(1.0f, s);
#pragma unroll
        for (int k = 0; k < HB; ++k)
            bm[wib * 256 + k * 16 + c] = R[k] * r;
        lamB[wib * 16 + c] = lam + m1 + __logf(s);
    }
    __syncthreads();

    // ---- block fold: 4 warp-mats -> 1 block-mat -> gmem ----
    if (wib < 2)
        mat_product2(bm, lamB, bm + 4 * 256, lamB + 4 * 16, wib, lane, sw[wib], false);
    __syncthreads();
    if (wib == 0)
        mat_product2(bm + 4 * 256, lamB + 4 * 16,
                     g_mats + (size_t)(b * NMB + blk) * 256,
                     g_lam  + (size_t)(b * NMB + blk) * 16,
                     0, lane, sw[0], false);

    // ---- last-block election ----
    __threadfence();
    __syncthreads();
    if (threadIdx.x == 0) {
        int old = atomicAdd(&g_cnt[b], 1);
        s_last = (old == BPB - 1);
        if (old == BPB - 1) g_cnt[b] = 0;
    }
    __syncthreads();
    if (!s_last) return;

    // ---- tree combine over 16 block-mats ----
    float* X = U.cb.X; float* lamX = U.cb.lamX;
    float* Y = bm;     float* lamY = lamB;
    const float* gM = g_mats + (size_t)b * NMB * 256;
    const float* gL = g_lam  + (size_t)b * NMB * 16;

    mat_product2(gM, gL, X, lamX, wib,     lane, sw[wib], true);
    mat_product2(gM, gL, X, lamX, wib + 4, lane, sw[wib], true);
    __syncthreads();
    mat_product2(X, lamX, Y, lamY, wib, lane, sw[wib], false);
    __syncthreads();
    if (wib < 2) mat_product2(Y, lamY, X, lamX, wib, lane, sw[wib], false);
    __syncthreads();
    if (wib == 0) mat_product2(X, lamX, Y, lamY, 0, lane, sw[0], false);
    __syncthreads();

    if (wib == 0) {
        const size_t rb = (size_t)b * T1;
        const int a0i = actions[(size_t)b * MAXT];

        float f0 = startl[rb * 16 + c] + alogp[(rb * 16 + (size_t)c) * 18 + a0i];
        float t = lamY[c] + f0;
        float F0 = t;
        F0 = fmaxf(F0, __shfl_xor_sync(0xffffffffu, F0, 1));
        F0 = fmaxf(F0, __shfl_xor_sync(0xffffffffu, F0, 2));
        F0 = fmaxf(F0, __shfl_xor_sync(0xffffffffu, F0, 4));
        F0 = fmaxf(F0, __shfl_xor_sync(0xffffffffu, F0, 8));
        if (lane < 16) sw[0][c] = __expf(t - F0);
        __syncwarp();
        const float4* M4 = (const float4*)Y;
        const float4* W4 = (const float4*)sw[0];
        float4 m0 = M4[c * 4 + 0], m1 = M4[c * 4 + 1];
        float4 m2 = M4[c * 4 + 2], m3 = M4[c * 4 + 3];
        float4 w0 = W4[0], w1 = W4[1], w2 = W4[2], w3 = W4[3];
        float d0 = fmaf(m0.x, w0.x, m0.y * w0.y) + fmaf(m0.z, w0.z, m0.w * w0.w);
        float d1 = fmaf(m1.x, w1.x, m1.y * w1.y) + fmaf(m1.z, w1.z, m1.w * w1.w);
        float d2 = fmaf(m2.x, w2.x, m2.y * w2.y) + fmaf(m2.z, w2.z, m2.w * w2.w);
        float d3 = fmaf(m3.x, w3.x, m3.y * w3.y) + fmaf(m3.z, w3.z, m3.w * w3.w);
        float v = (d0 + d1) + (d2 + d3);

        float u = stopl[((rb + (size_t)len) * 16 + (size_t)c) * 2];
        float mS = u;
        mS = fmaxf(mS, __shfl_xor_sync(0xffffffffu, mS, 1));
        mS = fmaxf(mS, __shfl_xor_sync(0xffffffffu, mS, 2));
        mS = fmaxf(mS, __shfl_xor_sync(0xffffffffu, mS, 4));
        mS = fmaxf(mS, __shfl_xor_sync(0xffffffffu, mS, 8));
        float term = __expf(u - mS) * v;
        term += __shfl_xor_sync(0xffffffffu, term, 1);
        term += __shfl_xor_sync(0xffffffffu, term, 2);
        term += __shfl_xor_sync(0xffffffffu, term, 4);
        term += __shfl_xor_sync(0xffffffffu, term, 8);

        if (lane == 0) {
            g_partial[b] = -(F0 + mS + __logf(term));
            __threadfence();
            int old2 = atomicAdd(&g_cnt2, 1);
            s_last2 = (old2 == NB - 1);
            if (old2 == NB - 1) g_cnt2 = 0;
        }
    }
    __syncthreads();

    if (s_last2 && wib == 0) {
        float v = ldcg(&g_partial[lane]) + ldcg(&g_partial[lane + 32]);
        v += __shfl_xor_sync(0xffffffffu, v, 1);
        v += __shfl_xor_sync(0xffffffffu, v, 2);
        v += __shfl_xor_sync(0xffffffffu, v, 4);
        v += __shfl_xor_sync(0xffffffffu, v, 8);
        v += __shfl_xor_sync(0xffffffffu, v, 16);
        if (lane == 0) *out = v;
    }
}

extern "C" void kernel_launch(void* const* d_in, const int* in_sizes, int n_in,
                              void* d_out, int out_size)
{
    const float* alogp   = (const float*)d_in[0];
    const float* stopl   = (const float*)d_in[1];
    const float* startl  = (const float*)d_in[2];
    const int*   actions = (const int*)d_in[3];
    const int*   lengths = (const int*)d_in[4];
    float* out = (float*)d_out;

    hmm_fused<<<NB * BPB, 128>>>(alogp, stopl, startl, actions, lengths, out);
}

// round 12
// speedup vs baseline: 1.2752x; 1.0465x over previous
#include <cuda_runtime.h>

// Problem constants (fixed by the dataset)
#define NB   64          // batch
#define T1   4097        // maxT+1
#define MAXT 4096
#define HB   16          // hidden states
#define CL   32          // chunk length (steps per chunk)
#define D    8           // steps per phase
#define PH   4           // phases per chunk (CL / D)
#define BPB  16          // blocks per batch
#define NMB  16          // block-level matrices per batch

// Scratch: per (batch, block) folded transfer matrix (256 steps each).
__device__ float g_mats[NB * NMB * HB * HB];   // 1 MB
__device__ float g_lam[NB * NMB * HB];
__device__ float g_partial[NB];
__device__ int   g_cnt[NB];     // zero-init; self-resetting each call
__device__ int   g_cnt2;        // zero-init; self-resetting each call

__device__ __forceinline__ float ldcg(const float* p) {
    float v; asm volatile("ld.global.cg.f32 %0,[%1];" : "=f"(v) : "l"(p)); return v;
}
__device__ __forceinline__ float4 ldcg4(const float* p) {
    float4 v;
    asm volatile("ld.global.cg.v4.f32 {%0,%1,%2,%3},[%4];"
                 : "=f"(v.x), "=f"(v.y), "=f"(v.z), "=f"(v.w) : "l"(p));
    return v;
}

// Tree product: C_true = A_true * P_true (A later, P earlier).
__device__ __forceinline__ void mat_product2(
    const float* __restrict__ srcM, const float* __restrict__ srcLam,
    float* __restrict__ dstM, float* __restrict__ dstLam,
    int pidx, int lane, float* __restrict__ sw, bool from_gmem)
{
    const int c = lane & 15;
    const int h = lane >> 4;                    // rows [8h, 8h+8)
    const float* Pm = srcM + (size_t)(2 * pidx) * 256;
    const float* Am = srcM + (size_t)(2 * pidx + 1) * 256;
    float lamP, lamA;
    if (from_gmem) {
        lamP = ldcg(srcLam + (2 * pidx) * 16 + c);
        lamA = ldcg(srcLam + (2 * pidx + 1) * 16 + c);
    } else {
        lamP = srcLam[(2 * pidx) * 16 + c];
        lamA = srcLam[(2 * pidx + 1) * 16 + c];
    }
    float mA = lamA;
    mA = fmaxf(mA, __shfl_xor_sync(0xffffffffu, mA, 1));
    mA = fmaxf(mA, __shfl_xor_sync(0xffffffffu, mA, 2));
    mA = fmaxf(mA, __shfl_xor_sync(0xffffffffu, mA, 4));
    mA = fmaxf(mA, __shfl_xor_sync(0xffffffffu, mA, 8));
    if (lane < 16) sw[c] = __expf(lamA - mA);
    __syncwarp();
    float w[16];
#pragma unroll
    for (int j = 0; j < 16; ++j)
        w[j] = sw[j] * (from_gmem ? ldcg(Pm + j * 16 + c) : Pm[j * 16 + c]);
    __syncwarp();
    float Cv[8];
#pragma unroll
    for (int k8 = 0; k8 < 8; ++k8) {
        float4 a0, a1, a2, a3;
        const float* Ar = Am + (h * 8 + k8) * 16;
        if (from_gmem) { a0 = ldcg4(Ar); a1 = ldcg4(Ar + 4); a2 = ldcg4(Ar + 8); a3 = ldcg4(Ar + 12); }
        else { const float4* A4 = (const float4*)Ar; a0 = A4[0]; a1 = A4[1]; a2 = A4[2]; a3 = A4[3]; }
        float d0 = fmaf(a0.x, w[0],  a0.y * w[1])  + fmaf(a0.z, w[2],  a0.w * w[3]);
        float d1 = fmaf(a1.x, w[4],  a1.y * w[5])  + fmaf(a1.z, w[6],  a1.w * w[7]);
        float d2 = fmaf(a2.x, w[8],  a2.y * w[9])  + fmaf(a2.z, w[10], a2.w * w[11]);
        float d3 = fmaf(a3.x, w[12], a3.y * w[13]) + fmaf(a3.z, w[14], a3.w * w[15]);
        Cv[k8] = (d0 + d1) + (d2 + d3);
    }
    float s = Cv[0];
#pragma unroll
    for (int k8 = 1; k8 < 8; ++k8) s = fmaxf(s, Cv[k8]);
    s = fmaxf(s, __shfl_xor_sync(0xffffffffu, s, 16));   // combine halves
    float r = __fdividef(1.0f, s);
#pragma unroll
    for (int k8 = 0; k8 < 8; ++k8)
        dstM[pidx * 256 + (h * 8 + k8) * 16 + c] = Cv[k8] * r;
    if (lane < 16) dstLam[pidx * 16 + c] = lamP + mA + __logf(s);
}

// Smem union: producer/consumer e-vector ring vs post-stream fold/combine bufs.
union __align__(16) SmemU {
    float ring[2][8][D][48];          // 24576 B: [buf][chunk-in-block][step][48]
    struct {
        float m1[4][HB][HB + 1];
        float lam1[4][HB];
        float X[8 * 256];
        float lamX[8 * 16];
    } post;
};

// ===========================================================================
// Warp-specialized fused kernel.
// 256 threads: warps 0-3 consume (recurrence, smem-only), warps 4-7 produce
// (gather alogp/stop/start, compute exps, stream e-vectors into the ring).
// Phases of D=8 steps, double-buffered, one __syncthreads per phase.
// Producer warp k feeds consumer warp k's two chunks (halves).
// ===========================================================================
__global__ __launch_bounds__(256, 3) void hmm_fused(
    const float* __restrict__ alogp,
    const float* __restrict__ stopl,
    const float* __restrict__ startl,
    const int* __restrict__ actions,
    const int* __restrict__ lengths,
    float* __restrict__ out)
{
    const int wib  = threadIdx.x >> 5;
    const int lane = threadIdx.x & 31;
    const int b    = blockIdx.x >> 4;             // 64 batches
    const int blk  = blockIdx.x & 15;             // 16 blocks per batch
    const int pw   = wib & 3;                     // role-local warp id 0..3
    const int pr   = blk * 4 + pw;                // chunk-pair id within batch
    const int sub  = lane >> 4;
    const int c    = lane & 15;
    const int ch   = pr * 2 + sub;                // 128 chunks per batch
    const int i0   = 1 + ch * CL;

    __shared__ SmemU U;
    __shared__ __align__(16) float bm[6 * 256];
    __shared__ float lamB[6 * 16];
    __shared__ __align__(16) float sw[4][16];
    __shared__ int s_last, s_last2;

    const int len = lengths[b];
    int nact = max(0, min(len - i0, min(CL, MAXT - i0)));

    float p[HB];
#pragma unroll
    for (int k = 0; k < HB; ++k) p[k] = (k == c) ? 1.0f : 0.0f;
    float lam = 0.0f;

    const unsigned idx16_0 = ((unsigned)b * T1 + (unsigned)i0) * 16u + (unsigned)c;
    const unsigned abase   = ((unsigned)b << 12) + (unsigned)i0;
    const float2* stop2 = (const float2*)stopl;

    // ---- streaming pipeline: PH fill phases, PH eat phases, offset by 1 ----
    for (int ph = 0; ph <= PH; ++ph) {
        if (wib >= 4 && ph < PH) {
            // PRODUCER: gather D steps, compute exps, store e-vectors.
            const int t0 = ph * D;
            int   av[D];
#pragma unroll
            for (int u = 0; u < D; ++u) {
                int t = t0 + u;
                av[u] = (t < nact) ? __ldg(actions + abase + (unsigned)t) : 0;
            }
            float2 s2[D]; float st[D], al[D];
#pragma unroll
            for (int u = 0; u < D; ++u) {
                int t = t0 + u;
                if (t < nact) {
                    unsigned idx = idx16_0 + (unsigned)t * 16u;
                    s2[u] = __ldg(stop2 + idx);
                    st[u] = __ldg(startl + idx);
                    al[u] = __ldg(alogp + (size_t)idx * 18u + (unsigned)av[u]);
                }
            }
            float* rb = &U.ring[ph & 1][pw * 2 + sub][0][0];
#pragma unroll
            for (int u = 0; u < D; ++u) {
                int t = t0 + u;
                float* vb = rb + u * 48;
                if (t < nact) {
                    vb[c]      = __expf(s2[u].x);            // eb
                    vb[16 + c] = __expf(al[u] + st[u]);      // eas
                    vb[32 + c] = __expf(al[u] + s2[u].y);    // eao
                } else {
                    vb[c] = 0.f; vb[16 + c] = 0.f; vb[32 + c] = 0.f;
                }
            }
        }
        if (wib < 4 && ph > 0) {
            // CONSUMER: recurrence over D steps of the previous phase.
            const int t0 = (ph - 1) * D;
            const float* rb = &U.ring[(ph - 1) & 1][wib * 2 + sub][0][0];
#pragma unroll
            for (int u = 0; u < D; ++u) {
                int t = t0 + u;
                if (t >= nact) break;          // uniform within each half-warp
                const float4* E = (const float4*)(rb + u * 48);
                float4 e0 = E[0], e1 = E[1], e2 = E[2],  e3 = E[3];
                float t0d = fmaf(e0.x, p[0],  e0.y * p[1])  + fmaf(e0.z, p[2],  e0.w * p[3]);
                float t1d = fmaf(e1.x, p[4],  e1.y * p[5])  + fmaf(e1.z, p[6],  e1.w * p[7]);
                float t2d = fmaf(e2.x, p[8],  e2.y * p[9])  + fmaf(e2.z, p[10], e2.w * p[11]);
                float t3d = fmaf(e3.x, p[12], e3.y * p[13]) + fmaf(e3.z, p[14], e3.w * p[15]);
                float s = (t0d + t1d) + (t2d + t3d);
                float4 a0 = E[4], a1 = E[5], a2 = E[6],  a3 = E[7];
                float4 o0 = E[8], o1 = E[9], o2 = E[10], o3 = E[11];
                p[0]  = fmaf(o0.x, p[0],  a0.x * s);
                p[1]  = fmaf(o0.y, p[1],  a0.y * s);
                p[2]  = fmaf(o0.z, p[2],  a0.z * s);
                p[3]  = fmaf(o0.w, p[3],  a0.w * s);
                p[4]  = fmaf(o1.x, p[4],  a1.x * s);
                p[5]  = fmaf(o1.y, p[5],  a1.y * s);
                p[6]  = fmaf(o1.z, p[6],  a1.z * s);
                p[7]  = fmaf(o1.w, p[7],  a1.w * s);
                p[8]  = fmaf(o2.x, p[8],  a2.x * s);
                p[9]  = fmaf(o2.y, p[9],  a2.y * s);
                p[10] = fmaf(o2.z, p[10], a2.z * s);
                p[11] = fmaf(o2.w, p[11], a2.w * s);
                p[12] = fmaf(o3.x, p[12], a3.x * s);
                p[13] = fmaf(o3.y, p[13], a3.y * s);
                p[14] = fmaf(o3.z, p[14], a3.z * s);
                p[15] = fmaf(o3.w, p[15], a3.w * s);
                if ((t & 3) == 3) {            // renorm every 4 steps
                    float r = __fdividef(1.0f, s);
                    lam += __logf(s);
#pragma unroll
                    for (int k = 0; k < HB; ++k) p[k] *= r;
                }
            }
        }
        __syncthreads();
    }

    // ---- warp fold (consumer warps): R_true = M1_true * M0_true ----
    if (wib < 4) {
        if (sub == 1) {
#pragma unroll
            for (int k = 0; k < HB; ++k) U.post.m1[wib][c][k] = p[k];
            U.post.lam1[wib][c] = lam;
        }
        __syncwarp();
        if (sub == 0) {
            float m1 = U.post.lam1[wib][0];
#pragma unroll
            for (int j = 1; j < HB; ++j) m1 = fmaxf(m1, U.post.lam1[wib][j]);
            float R[HB];
#pragma unroll
            for (int k = 0; k < HB; ++k) R[k] = 0.0f;
#pragma unroll
            for (int j = 0; j < HB; ++j) {
                float wj = p[j] * __expf(U.post.lam1[wib][j] - m1);
                const float* Aj = &U.post.m1[wib][j][0];
#pragma unroll
                for (int k = 0; k < HB; ++k) R[k] = fmaf(wj, Aj[k], R[k]);
            }
            float s = R[0];
#pragma unroll
            for (int k = 1; k < HB; ++k) s = fmaxf(s, R[k]);
            float r = __fdividef(1.0f, s);
#pragma unroll
            for (int k = 0; k < HB; ++k)
                bm[wib * 256 + k * 16 + c] = R[k] * r;
            lamB[wib * 16 + c] = lam + m1 + __logf(s);
        }
    }
    __syncthreads();

    // ---- block fold: 4 warp-mats -> 1 block-mat -> gmem ----
    if (wib < 2)
        mat_product2(bm, lamB, bm + 4 * 256, lamB + 4 * 16, wib, lane, sw[wib], false);
    __syncthreads();
    if (wib == 0)
        mat_product2(bm + 4 * 256, lamB + 4 * 16,
                     g_mats + (size_t)(b * NMB + blk) * 256,
                     g_lam  + (size_t)(b * NMB + blk) * 16,
                     0, lane, sw[0], false);

    // ---- last-block election ----
    __threadfence();
    __syncthreads();
    if (threadIdx.x == 0) {
        int old = atomicAdd(&g_cnt[b], 1);
        s_last = (old == BPB - 1);
        if (old == BPB - 1) g_cnt[b] = 0;
    }
    __syncthreads();
    if (!s_last) return;

    // ---- tree combine over 16 block-mats (consumer warps work) ----
    float* X = U.post.X; float* lamX = U.post.lamX;
    float* Y = bm;       float* lamY = lamB;
    const float* gM = g_mats + (size_t)b * NMB * 256;
    const float* gL = g_lam  + (size_t)b * NMB * 16;

    if (wib < 4) {
        mat_product2(gM, gL, X, lamX, wib,     lane, sw[wib], true);
        mat_product2(gM, gL, X, lamX, wib + 4, lane, sw[wib], true);
    }
    __syncthreads();
    if (wib < 4) mat_product2(X, lamX, Y, lamY, wib, lane, sw[wib], false);
    __syncthreads();
    if (wib < 2) mat_product2(Y, lamY, X, lamX, wib, lane, sw[wib], false);
    __syncthreads();
    if (wib == 0) mat_product2(X, lamX, Y, lamY, 0, lane, sw[0], false);
    __syncthreads();

    if (wib == 0) {
        const size_t rb = (size_t)b * T1;
        const int a0i = actions[(size_t)b * MAXT];

        float f0 = startl[rb * 16 + c] + alogp[(rb * 16 + (size_t)c) * 18 + a0i];
        float t = lamY[c] + f0;
        float F0 = t;
        F0 = fmaxf(F0, __shfl_xor_sync(0xffffffffu, F0, 1));
        F0 = fmaxf(F0, __shfl_xor_sync(0xffffffffu, F0, 2));
        F0 = fmaxf(F0, __shfl_xor_sync(0xffffffffu, F0, 4));
        F0 = fmaxf(F0, __shfl_xor_sync(0xffffffffu, F0, 8));
        if (lane < 16) sw[0][c] = __expf(t - F0);
        __syncwarp();
        const float4* M4 = (const float4*)Y;
        const float4* W4 = (const float4*)sw[0];
        float4 m0 = M4[c * 4 + 0], m1 = M4[c * 4 + 1];
        float4 m2 = M4[c * 4 + 2], m3 = M4[c * 4 + 3];
        float4 w0 = W4[0], w1 = W4[1], w2 = W4[2], w3 = W4[3];
        float d0 = fmaf(m0.x, w0.x, m0.y * w0.y) + fmaf(m0.z, w0.z, m0.w * w0.w);
        float d1 = fmaf(m1.x, w1.x, m1.y * w1.y) + fmaf(m1.z, w1.z, m1.w * w1.w);
        float d2 = fmaf(m2.x, w2.x, m2.y * w2.y) + fmaf(m2.z, w2.z, m2.w * w2.w);
        float d3 = fmaf(m3.x, w3.x, m3.y * w3.y) + fmaf(m3.z, w3.z, m3.w * w3.w);
        float v = (d0 + d1) + (d2 + d3);

        float u = stopl[((rb + (size_t)len) * 16 + (size_t)c) * 2];
        float mS = u;
        mS = fmaxf(mS, __shfl_xor_sync(0xffffffffu, mS, 1));
        mS = fmaxf(mS, __shfl_xor_sync(0xffffffffu, mS, 2));
        mS = fmaxf(mS, __shfl_xor_sync(0xffffffffu, mS, 4));
        mS = fmaxf(mS, __shfl_xor_sync(0xffffffffu, mS, 8));
        float term = __expf(u - mS) * v;
        term += __shfl_xor_sync(0xffffffffu, term, 1);
        term += __shfl_xor_sync(0xffffffffu, term, 2);
        term += __shfl_xor_sync(0xffffffffu, term, 4);
        term += __shfl_xor_sync(0xffffffffu, term, 8);

        if (lane == 0) {
            g_partial[b] = -(F0 + mS + __logf(term));
            __threadfence();
            int old2 = atomicAdd(&g_cnt2, 1);
            s_last2 = (old2 == NB - 1);
            if (old2 == NB - 1) g_cnt2 = 0;
        }
    }
    __syncthreads();

    if (s_last2 && wib == 0) {
        float v = ldcg(&g_partial[lane]) + ldcg(&g_partial[lane + 32]);
        v += __shfl_xor_sync(0xffffffffu, v, 1);
        v += __shfl_xor_sync(0xffffffffu, v, 2);
        v += __shfl_xor_sync(0xffffffffu, v, 4);
        v += __shfl_xor_sync(0xffffffffu, v, 8);
        v += __shfl_xor_sync(0xffffffffu, v, 16);
        if (lane == 0) *out = v;
    }
}

extern "C" void kernel_launch(void* const* d_in, const int* in_sizes, int n_in,
                              void* d_out, int out_size)
{
    const float* alogp   = (const float*)d_in[0];
    const float* stopl   = (const float*)d_in[1];
    const float* startl  = (const float*)d_in[2];
    const int*   actions = (const int*)d_in[3];
    const int*   lengths = (const int*)d_in[4];
    float* out = (float*)d_out;

    hmm_fused<<<NB * BPB, 256>>>(alogp, stopl, startl, actions, lengths, out);
}